// round 1
// baseline (speedup 1.0000x reference)
#include <cuda_runtime.h>
#include <cuda_bf16.h>

// DenseIouPred: 72x72 IoU map around ind[0] with window radius r.
// Reference only uses batch/seq element [0,0]. Scatter over window offsets
// inverts to a per-pixel gather because valid offsets map 1:1 to in-range
// pixels and the feature-gather index equals the pixel's own flat index.

#define W 72
#define H 72
#define NPIX (W * H)

__global__ void dense_iou_kernel(const float* __restrict__ out0,   // output[0,0] base: (4, W, H)
                                 const int*   __restrict__ ind,    // ind[0,0,0]
                                 const float* __restrict__ tgt,    // target[0,0,:4]
                                 const int*   __restrict__ radius_p,
                                 float*       __restrict__ dst)    // (W, H)
{
    int i = blockIdx.x * blockDim.x + threadIdx.x;
    if (i >= NPIX) return;

    const int row = i / H;      // map row (center_h axis)
    const int col = i % H;      // map col (center_w axis)

    const int ind0 = ind[0];
    const int cw = ind0 % W;
    const int ch = ind0 / W;
    const int r  = radius_p ? radius_p[0] : 10;

    const int rw = col - cw;    // RW offset
    const int rh = row - ch;    // RH offset

    float v = 0.0f;
    if (rw >= -r && rw <= r && rh >= -r && rh <= r) {
        const float frw = (float)rw;
        const float frh = (float)rh;
        const float twl = tgt[0] + frw;
        const float twr = tgt[1] - frw;
        const float tht = tgt[2] + frh;
        const float thb = tgt[3] - frh;
        if (twl >= 0.0f && twr >= 0.0f && tht >= 0.0f && thb >= 0.0f) {
            // pred = output[0,0,c,row,col]; flat gather index == i for in-range pixels
            const float pl = out0[0 * NPIX + i];
            const float pr = out0[1 * NPIX + i];
            const float pt = out0[2 * NPIX + i];
            const float pb = out0[3 * NPIX + i];

            const float target_area = (twl + twr) * (tht + thb);
            const float pred_area   = (pl + pr) * (pt + pb);
            const float w_int = fminf(pl, twl) + fminf(pr, twr);
            const float h_int = fminf(pb, thb) + fminf(pt, tht);
            const float area_int = w_int * h_int;
            const float area_union = target_area + pred_area - area_int;
            v = (area_int + 1.0f) / (area_union + 1.0f);
        }
    }
    dst[i] = v;
}

extern "C" void kernel_launch(void* const* d_in, const int* in_sizes, int n_in,
                              void* d_out, int out_size)
{
    const float* output = (const float*)d_in[0];   // (128, 8, 4, 72, 72) fp32
    const int*   ind    = (const int*)  d_in[1];   // (128, 8, 1) int32
    const float* target = (const float*)d_in[2];   // (128, 8, 4) fp32
    const int*   radius = (n_in >= 4) ? (const int*)d_in[3] : nullptr;  // scalar int32
    float*       dst    = (float*)d_out;           // (72, 72) fp32

    const int threads = 256;
    const int blocks  = (NPIX + threads - 1) / threads;
    dense_iou_kernel<<<blocks, threads>>>(output, ind, target, radius, dst);
}